// round 1
// baseline (speedup 1.0000x reference)
#include <cuda_runtime.h>
#include <math.h>

#define T_TOKENS 16384
#define DDIM     2048
#define NEXP     256
#define TOPK     8
#define BM       64
#define BK       32

// Fused MoE gate: logits GEMM (fp32) + softmax + group-limited top-k routing.
// Block: 64 tokens x 256 experts. 256 threads = 8 warps.
// Thread (warp w, lane l) accumulates tokens [w*8 .. w*8+7] x experts
// {4l..4l+3} U {128+4l..128+4l+3}  -> each warp owns 8 full token rows,
// so softmax / group-mask / top-8 run in registers + shuffles only.
__global__ __launch_bounds__(256, 2)
void gate_kernel(const float* __restrict__ x,
                 const float* __restrict__ w,
                 const float* __restrict__ bias,
                 float* __restrict__ out_w,
                 float* __restrict__ out_i,
                 float* __restrict__ load)
{
    __shared__ float As[BM][BK];     // [token][k]
    __shared__ float Bs[BK][NEXP];   // [k][expert]

    const int tid   = threadIdx.x;
    const int lane  = tid & 31;
    const int warp  = tid >> 5;
    const int blockM = blockIdx.x * BM;

    float acc[8][8];
#pragma unroll
    for (int i = 0; i < 8; i++)
#pragma unroll
        for (int j = 0; j < 8; j++) acc[i][j] = 0.f;

    const int ar = tid >> 3;        // 0..31 (A row within half-tile)
    const int ac = (tid & 7) * 4;   // 0..28 (A col chunk)

    for (int kb = 0; kb < DDIM; kb += BK) {
        // --- load A tile: 64 rows x 32 k (float4, coalesced) ---
#pragma unroll
        for (int q = 0; q < 2; q++) {
            int r = ar + q * 32;
            float4 v = *reinterpret_cast<const float4*>(
                &x[(size_t)(blockM + r) * DDIM + kb + ac]);
            *reinterpret_cast<float4*>(&As[r][ac]) = v;
        }
        // --- load B tile: thread t = expert row t, 32 k values, transpose to Bs[k][n] ---
        {
            const float* wp = &w[(size_t)tid * DDIM + kb];
#pragma unroll
            for (int c = 0; c < 8; c++) {
                float4 v = *reinterpret_cast<const float4*>(wp + c * 4);
                Bs[c * 4 + 0][tid] = v.x;
                Bs[c * 4 + 1][tid] = v.y;
                Bs[c * 4 + 2][tid] = v.z;
                Bs[c * 4 + 3][tid] = v.w;
            }
        }
        __syncthreads();

#pragma unroll
        for (int k = 0; k < BK; k++) {
            float b0[4], b1[4];
            *reinterpret_cast<float4*>(b0) =
                *reinterpret_cast<const float4*>(&Bs[k][lane * 4]);
            *reinterpret_cast<float4*>(b1) =
                *reinterpret_cast<const float4*>(&Bs[k][lane * 4 + 128]);
#pragma unroll
            for (int i = 0; i < 8; i++) {
                float a = As[warp * 8 + i][k];   // broadcast (same addr all lanes)
#pragma unroll
                for (int j = 0; j < 4; j++) {
                    acc[i][j]     = fmaf(a, b0[j], acc[i][j]);
                    acc[i][4 + j] = fmaf(a, b1[j], acc[i][4 + j]);
                }
            }
        }
        __syncthreads();
    }

    // ------------------- routing epilogue (per warp, 8 tokens) -------------------
    // expert id for slot j: e(j) = (j<4) ? 4*lane + j : 128 + 4*lane + (j-4)
    float bia[8];
#pragma unroll
    for (int j = 0; j < 8; j++)
        bia[j] = bias[(j < 4) ? lane * 4 + j : 128 + lane * 4 + (j - 4)];

    for (int i = 0; i < 8; i++) {
        float* v = acc[i];

        // softmax over 256 logits (warp-wide)
        float mx = v[0];
#pragma unroll
        for (int j = 1; j < 8; j++) mx = fmaxf(mx, v[j]);
#pragma unroll
        for (int off = 16; off >= 1; off >>= 1)
            mx = fmaxf(mx, __shfl_xor_sync(0xffffffffu, mx, off));

        float s[8], sum = 0.f;
#pragma unroll
        for (int j = 0; j < 8; j++) { s[j] = expf(v[j] - mx); sum += s[j]; }
#pragma unroll
        for (int off = 16; off >= 1; off >>= 1)
            sum += __shfl_xor_sync(0xffffffffu, sum, off);
        float inv = 1.f / sum;

        float sel[8];
#pragma unroll
        for (int j = 0; j < 8; j++) { s[j] *= inv; sel[j] = s[j] + bia[j]; }

        // group scores: lane's slots 0..3 -> group (lane>>3); slots 4..7 -> group 4+(lane>>3)
        float g0 = fmaxf(fmaxf(sel[0], sel[1]), fmaxf(sel[2], sel[3]));
        float g1 = fmaxf(fmaxf(sel[4], sel[5]), fmaxf(sel[6], sel[7]));
#pragma unroll
        for (int off = 1; off < 8; off <<= 1) {
            g0 = fmaxf(g0, __shfl_xor_sync(0xffffffffu, g0, off));
            g1 = fmaxf(g1, __shfl_xor_sync(0xffffffffu, g1, off));
        }
        float g[8];
#pragma unroll
        for (int q = 0; q < 4; q++) {
            g[q]     = __shfl_sync(0xffffffffu, g0, q * 8);
            g[4 + q] = __shfl_sync(0xffffffffu, g1, q * 8);
        }
        // top-4 groups (tie -> lower group index, matching lax.top_k)
        unsigned kept = 0;
#pragma unroll
        for (int t = 0; t < 8; t++) {
            int rank = 0;
#pragma unroll
            for (int u = 0; u < 8; u++)
                rank += (g[u] > g[t]) || (g[u] == g[t] && u < t);
            if (rank < 4) kept |= (1u << t);
        }
        int myg = lane >> 3;
        if (!((kept >> myg) & 1u))       { sel[0] = sel[1] = sel[2] = sel[3] = -INFINITY; }
        if (!((kept >> (4 + myg)) & 1u)) { sel[4] = sel[5] = sel[6] = sel[7] = -INFINITY; }

        // iterative top-8 (descending; tie -> smaller expert index)
        float wsel = 0.f; int isel = 0;
#pragma unroll
        for (int kk = 0; kk < 8; kk++) {
            float bv = sel[0]; int bj = 0;
#pragma unroll
            for (int j = 1; j < 8; j++)
                if (sel[j] > bv) { bv = sel[j]; bj = j; }
            int   be = (bj < 4) ? lane * 4 + bj : 128 + lane * 4 + (bj - 4);
            float bs = s[bj];
#pragma unroll
            for (int off = 16; off >= 1; off >>= 1) {
                float ov = __shfl_xor_sync(0xffffffffu, bv, off);
                int   oe = __shfl_xor_sync(0xffffffffu, be, off);
                float os = __shfl_xor_sync(0xffffffffu, bs, off);
                if (ov > bv || (ov == bv && oe < be)) { bv = ov; be = oe; bs = os; }
            }
            if (lane == kk) { wsel = bs * 2.5f; isel = be; }
            // owning lane retires the winner
            int owner = (be & 127) >> 2;
            if (lane == owner) {
                int j = (be & 3) + ((be >= 128) ? 4 : 0);
                sel[j] = -INFINITY;
            }
        }

        int tok = blockM + warp * 8 + i;
        if (lane < 8) {
            out_w[tok * TOPK + lane] = wsel;
            out_i[tok * TOPK + lane] = (float)isel;
            atomicAdd(&load[isel], 1.0f);
        }
    }
}

extern "C" void kernel_launch(void* const* d_in, const int* in_sizes, int n_in,
                              void* d_out, int out_size)
{
    const float* x    = (const float*)d_in[0];
    const float* w    = (const float*)d_in[1];
    const float* bias = (const float*)d_in[2];

    float* out   = (float*)d_out;
    float* out_w = out;                              // [T, 8] gating weights
    float* out_i = out + (size_t)T_TOKENS * TOPK;    // [T, 8] indices (as float)
    float* load  = out + (size_t)2 * T_TOKENS * TOPK;// [256]  expert load

    cudaMemsetAsync(load, 0, NEXP * sizeof(float), 0);
    gate_kernel<<<T_TOKENS / BM, 256>>>(x, w, bias, out_w, out_i, load);
}